// round 11
// baseline (speedup 1.0000x reference)
#include <cuda_runtime.h>
#include <cstdint>

// Conv2d N=16,C=128,H=W=56,K=128,3x3,pad1 as 9 shifted GEMMs using
// mma.sync.m16n8k16.f32.f16.f16.f32 (base PTX).
// CTA = 64k x 56 pos (ONE output row), 4 warps (each 16k x 56n -> acc=28),
// 128 threads, grid 1792, occ 6 -> tiny wave-quantization tail.
// No W smem: A fragments = 2x LDG.128/stage from L2-resident g_Wh.
// Barriers only at X c-group boundaries (4 total); warps self-paced.

typedef uint32_t u32;

#define X_ELEMS 2928                 // u32 half2: [kk:2][lq:4][row:3][122]
#define XB(i)   ((i) * X_ELEMS)
#define SMEM_BYTES (2 * X_ELEMS * 4) // 23424

__device__ u32 g_Wh[36 * 2048];      // [slab:36][mgrp:4][mt:2][kk:2][lane:32][4] fp16x2

__global__ void prep_weights(const float* __restrict__ wt) {
    int idx = blockIdx.x * 256 + threadIdx.x;
    if (idx >= 36 * 2048) return;
    int slab   = idx >> 11;
    int within = idx & 2047;
    int vi   = within & 3;           // a-reg index a0..a3
    int lane = (within >> 2) & 31;
    int kk   = (within >> 7) & 1;
    int mt   = (within >> 8) & 1;
    int mgrp = (within >> 9) & 3;
    int cg = slab / 9, rs = slab % 9;
    int k  = mgrp * 32 + mt * 16 + (lane >> 2) + (vi & 1) * 8;
    int c0 = cg * 32 + kk * 16 + (lane & 3) * 2 + (vi >> 1) * 8;
    float v0 = wt[(size_t)k * 1152 + (size_t)c0 * 9 + rs];
    float v1 = wt[(size_t)k * 1152 + (size_t)(c0 + 1) * 9 + rs];
    u32 p;
    asm("cvt.rn.f16x2.f32 %0, %1, %2;" : "=r"(p) : "f"(v1), "f"(v0));
    g_Wh[idx] = p;
}

__global__ __launch_bounds__(128, 6)
void conv_mma(const float* __restrict__ in,
              const float* __restrict__ bias,
              float* __restrict__ out)
{
    extern __shared__ u32 sm[];

    const int tid = threadIdx.x;
    const int wid = tid >> 5, lid = tid & 31;
    const int lq = lid & 3, g = lid >> 2;

    // blockIdx.x = img*112 + row*2 + kt  (k-halves adjacent -> L2 X reuse)
    const int kt  = blockIdx.x & 1;
    const int h0  = (blockIdx.x >> 1) % 56;
    const int img = blockIdx.x / 112;
    const float* in_n = in + (size_t)img * 401408;

    // warp covers k = kt*64 + wid*16 .. +15  (old layout: mgrp, mt below)
    const int mgrp_old = kt * 2 + (wid >> 1);
    const int mt_old   = wid & 1;

    float acc[7][4];
    #pragma unroll
    for (int nt = 0; nt < 7; nt++)
        #pragma unroll
        for (int q = 0; q < 4; q++) acc[nt][q] = 0.f;

    // ---- X loader: LDG fp32 -> cvt.rn.f16x2 -> STS ----
    auto loadX = [&](int cg, int xb) {
        #pragma unroll 1
        for (int idx = tid; idx < 2784; idx += 128) {
            int wl  = idx % 58;
            int t   = idx / 58;          // 0..47
            int row = t >> 4;            // 0..2  (input row h0-1+row)
            int rem = t & 15;
            int kk_ = rem & 1;
            int lq_ = (rem >> 1) & 3;
            int hi  = rem >> 3;
            int hin = h0 - 1 + row;
            int win = wl - 1;
            int c0  = cg * 32 + kk_ * 16 + lq_ * 2 + hi * 8;
            float v0 = 0.f, v1 = 0.f;
            if (((unsigned)hin < 56u) & ((unsigned)win < 56u)) {
                const float* p = in_n + (size_t)c0 * 3136 + hin * 56 + win;
                v0 = __ldg(p);
                v1 = __ldg(p + 3136);
            }
            u32 pk;
            asm("cvt.rn.f16x2.f32 %0, %1, %2;" : "=r"(pk) : "f"(v1), "f"(v0));
            sm[XB(xb) + ((kk_ * 4 + lq_) * 3 + row) * 122 + wl * 2 + hi] = pk;
        }
    };

    // ---- prologue ----
    loadX(0, 0);
    __syncthreads();        // X(0) published
    loadX(1, 1);            // fills buf1 while stages 0-8 run

    #pragma unroll 1
    for (int s = 0; s < 36; s++) {
        if ((s % 9) == 0 && s > 0) {
            __syncthreads();                       // X(s/9) published; old buf free
            if (s < 27) loadX(s / 9 + 1, (s / 9 + 1) & 1);
        }

        const int rs = s % 9;
        const u32* Wg = g_Wh + (size_t)s * 2048 + mgrp_old * 512
                        + mt_old * 256 + lid * 4;
        const u32* Bb = sm + XB((s / 9) & 1) + lq * 366
                        + (rs / 3) * 122 + (g + rs % 3) * 2;

        #pragma unroll
        for (int kk = 0; kk < 2; kk++) {
            uint4 av = __ldg(reinterpret_cast<const uint4*>(Wg + kk * 128));
            u32 b[7][2];
            #pragma unroll
            for (int nt = 0; nt < 7; nt++) {
                uint2 v = *reinterpret_cast<const uint2*>(
                              Bb + kk * 1464 + nt * 16);
                b[nt][0] = v.x;
                b[nt][1] = v.y;
            }
            #pragma unroll
            for (int nt = 0; nt < 7; nt++)
                asm volatile(
                    "mma.sync.aligned.m16n8k16.row.col.f32.f16.f16.f32 "
                    "{%0,%1,%2,%3}, {%4,%5,%6,%7}, {%8,%9}, {%0,%1,%2,%3};"
                    : "+f"(acc[nt][0]), "+f"(acc[nt][1]),
                      "+f"(acc[nt][2]), "+f"(acc[nt][3])
                    : "r"(av.x), "r"(av.y), "r"(av.z), "r"(av.w),
                      "r"(b[nt][0]), "r"(b[nt][1]));
        }
    }

    // ---- epilogue: direct STG.64 + bias ----
    #pragma unroll
    for (int h = 0; h < 2; h++) {
        const int k = kt * 64 + wid * 16 + h * 8 + g;
        const float bv = __ldg(&bias[k]);
        float* op = out + (size_t)img * 401408 + (size_t)k * 3136
                    + h0 * 56 + lq * 2;
        #pragma unroll
        for (int nt = 0; nt < 7; nt++) {
            float2 v;
            v.x = acc[nt][2 * h + 0] + bv;
            v.y = acc[nt][2 * h + 1] + bv;
            *reinterpret_cast<float2*>(op + nt * 8) = v;
        }
    }
}

extern "C" void kernel_launch(void* const* d_in, const int* in_sizes, int n_in,
                              void* d_out, int out_size)
{
    const float* input  = (const float*)d_in[0];
    const float* weight = (const float*)d_in[1];
    const float* bias   = (const float*)d_in[2];
    float* out = (float*)d_out;

    cudaFuncSetAttribute(conv_mma, cudaFuncAttributeMaxDynamicSharedMemorySize,
                         SMEM_BYTES);

    prep_weights<<<(36 * 2048 + 255) / 256, 256>>>(weight);
    conv_mma<<<1792, 128, SMEM_BYTES>>>(input, bias, out);
}

// round 12
// speedup vs baseline: 1.3874x; 1.3874x over previous
#include <cuda_runtime.h>
#include <cstdint>

// Conv2d N=16,C=128,H=W=56,K=128,3x3,pad1 as 9 shifted GEMMs using
// mma.sync.m16n8k16.f32.f16.f16.f32 (base PTX).
// CTA = 128k x 112 pos (2 rows x 56 w), **512 threads / 16 warps**
// (8 mgrp of 16k x 2 rows) -> 8 warps/SMSP for latency coverage.
// 3-slot cp.async W ring (8KB slabs, 1 instr/thread), double-buffered X
// (LDG->cvt.rn.f16x2->STS), one barrier per stage. acc=28 regs/thread.

typedef uint32_t u32;

#define X_ELEMS 3904                 // u32 half2: [kk:2][lq:4][row:4][122]
#define W_ELEMS 2048                 // u32: [mgrp:8][kk:2][lane:32][4]
#define XB(i)   ((i) * X_ELEMS)
#define WB(i)   (2 * X_ELEMS + (i) * W_ELEMS)
#define SMEM_BYTES ((2 * X_ELEMS + 3 * W_ELEMS) * 4)   // 55808

__device__ u32 g_Wh[36 * 2048];      // fragment-ordered fp16x2 slabs

__global__ void prep_weights(const float* __restrict__ wt) {
    int idx = blockIdx.x * 256 + threadIdx.x;
    if (idx >= 36 * 2048) return;
    int slab   = idx >> 11;
    int within = idx & 2047;
    int vi   = within & 3;           // a-reg index a0..a3
    int lane = (within >> 2) & 31;
    int kk   = (within >> 7) & 1;
    int mgrp = (within >> 8) & 7;
    int cg = slab / 9, rs = slab % 9;
    int k  = mgrp * 16 + (lane >> 2) + (vi & 1) * 8;
    int c0 = cg * 32 + kk * 16 + (lane & 3) * 2 + (vi >> 1) * 8;
    float v0 = wt[(size_t)k * 1152 + (size_t)c0 * 9 + rs];
    float v1 = wt[(size_t)k * 1152 + (size_t)(c0 + 1) * 9 + rs];
    u32 p;
    asm("cvt.rn.f16x2.f32 %0, %1, %2;" : "=r"(p) : "f"(v1), "f"(v0));
    g_Wh[idx] = p;
}

__global__ __launch_bounds__(512, 2)
void conv_mma(const float* __restrict__ in,
              const float* __restrict__ bias,
              float* __restrict__ out)
{
    extern __shared__ u32 sm[];
    u32 sbase;
    asm("{ .reg .u64 t; cvta.to.shared.u64 t, %1; cvt.u32.u64 %0, t; }"
        : "=r"(sbase) : "l"(sm));

    const int tid = threadIdx.x;
    const int wid = tid >> 5, lid = tid & 31;
    const int lq = lid & 3, g = lid >> 2;
    const int mgrp = wid & 7;             // warp m group (16 k each)
    const int wn = wid >> 3;              // warp output row (0/1)

    const int img = blockIdx.x / 28;
    const int h0  = (blockIdx.x % 28) * 2;
    const float* in_n = in + (size_t)img * 401408;

    float acc[7][4];
    #pragma unroll
    for (int nt = 0; nt < 7; nt++)
        #pragma unroll
        for (int q = 0; q < 4; q++) acc[nt][q] = 0.f;

    // ---- X loader: LDG fp32 -> cvt.rn.f16x2 -> STS (once per element) ----
    auto loadX = [&](int cg, int xb) {
        #pragma unroll 1
        for (int idx = tid; idx < 3712; idx += 512) {
            int wl  = idx % 58;
            int t   = idx / 58;
            int row = t & 3;
            int hi  = (t >> 2) & 1;
            int lq_ = (t >> 3) & 3;
            int kk_ = t >> 5;
            int hin = h0 - 1 + row;
            int win = wl - 1;
            int c0  = cg * 32 + kk_ * 16 + lq_ * 2 + hi * 8;
            float v0 = 0.f, v1 = 0.f;
            if (((unsigned)hin < 56u) & ((unsigned)win < 56u)) {
                const float* p = in_n + (size_t)c0 * 3136 + hin * 56 + win;
                v0 = __ldg(p);
                v1 = __ldg(p + 3136);
            }
            u32 pk;
            asm("cvt.rn.f16x2.f32 %0, %1, %2;" : "=r"(pk) : "f"(v1), "f"(v0));
            sm[XB(xb) + ((kk_ * 4 + lq_) * 4 + row) * 122 + wl * 2 + hi] = pk;
        }
    };

    // ---- async W loader: 8KB slab, exactly one cp.async per thread ----
    auto prefW = [&](int s, int slot) {
        const u32* src = g_Wh + (size_t)s * 2048;
        const u32 dstb = sbase + WB(slot) * 4;
        asm volatile("cp.async.ca.shared.global [%0], [%1], 16;"
                     :: "r"(dstb + tid * 16), "l"(src + tid * 4) : "memory");
        asm volatile("cp.async.commit_group;" ::: "memory");
    };

    // ---- prologue ----
    loadX(0, 0);
    prefW(0, 0);
    prefW(1, 1);

    #pragma unroll 1
    for (int s = 0; s < 36; s++) {
        if (s < 35) asm volatile("cp.async.wait_group 1;" ::: "memory");
        else        asm volatile("cp.async.wait_group 0;" ::: "memory");
        __syncthreads();   // W(s) + current X visible; prior consumers done

        if (s + 2 < 36) prefW(s + 2, (s + 2) % 3);
        if (s % 9 == 5 && s / 9 + 1 < 4) loadX(s / 9 + 1, (s / 9 + 1) & 1);

        const int rs = s % 9;
        const u32* Wb = sm + WB(s % 3) + mgrp * 256 + lid * 4;
        const u32* Bb = sm + XB((s / 9) & 1) + lq * 488
                        + (wn + rs / 3) * 122 + (g + rs % 3) * 2;

        #pragma unroll
        for (int kk = 0; kk < 2; kk++) {
            uint4 av = *reinterpret_cast<const uint4*>(Wb + kk * 128);
            u32 b[7][2];
            #pragma unroll
            for (int nt = 0; nt < 7; nt++) {
                uint2 v = *reinterpret_cast<const uint2*>(
                              Bb + kk * 1952 + nt * 16);
                b[nt][0] = v.x;
                b[nt][1] = v.y;
            }
            #pragma unroll
            for (int nt = 0; nt < 7; nt++)
                asm volatile(
                    "mma.sync.aligned.m16n8k16.row.col.f32.f16.f16.f32 "
                    "{%0,%1,%2,%3}, {%4,%5,%6,%7}, {%8,%9}, {%0,%1,%2,%3};"
                    : "+f"(acc[nt][0]), "+f"(acc[nt][1]),
                      "+f"(acc[nt][2]), "+f"(acc[nt][3])
                    : "r"(av.x), "r"(av.y), "r"(av.z), "r"(av.w),
                      "r"(b[nt][0]), "r"(b[nt][1]));
        }
    }

    // ---- epilogue: direct STG.64 + bias ----
    #pragma unroll
    for (int h = 0; h < 2; h++) {
        const int k = mgrp * 16 + h * 8 + g;
        const float bv = __ldg(&bias[k]);
        float* op = out + (size_t)img * 401408 + (size_t)k * 3136
                    + (h0 + wn) * 56 + lq * 2;
        #pragma unroll
        for (int nt = 0; nt < 7; nt++) {
            float2 v;
            v.x = acc[nt][2 * h + 0] + bv;
            v.y = acc[nt][2 * h + 1] + bv;
            *reinterpret_cast<float2*>(op + nt * 8) = v;
        }
    }
}

extern "C" void kernel_launch(void* const* d_in, const int* in_sizes, int n_in,
                              void* d_out, int out_size)
{
    const float* input  = (const float*)d_in[0];
    const float* weight = (const float*)d_in[1];
    const float* bias   = (const float*)d_in[2];
    float* out = (float*)d_out;

    cudaFuncSetAttribute(conv_mma, cudaFuncAttributeMaxDynamicSharedMemorySize,
                         SMEM_BYTES);

    prep_weights<<<(36 * 2048 + 255) / 256, 256>>>(weight);
    conv_mma<<<448, 512, SMEM_BYTES>>>(input, bias, out);
}

// round 13
// speedup vs baseline: 1.6204x; 1.1679x over previous
#include <cuda_runtime.h>
#include <cstdint>

// Conv2d N=16,C=128,H=W=56,K=128,3x3,pad1 as 9 shifted GEMMs using
// mma.sync.m16n8k16.f32.f16.f16.f32 (base PTX).
// CTA = 128k x 112 pos (2 rows x 56 w), 8 warps — R8 structure — but
// register-capped to 85 via __launch_bounds__(256,3) so THREE CTAs fit
// per SM: grid 448 vs 444 resident = 1.01 waves (kills the 33% wave-
// quantization tail of the occ-2 version). A-frag loaded per-mt to keep
// liveness (acc56 + b14 + av4) under the cap.

typedef uint32_t u32;

#define X_ELEMS 3904                 // u32 half2: [kk:2][lq:4][row:4][122]
#define W_ELEMS 2048                 // u32: [mgrp:4][mt:2][kk:2][lane:32][4]
#define XB(i)   ((i) * X_ELEMS)
#define WB(i)   (2 * X_ELEMS + (i) * W_ELEMS)
#define SMEM_BYTES ((2 * X_ELEMS + 3 * W_ELEMS) * 4)   // 55808

__device__ u32 g_Wh[36 * 2048];      // fragment-ordered fp16x2 slabs

__global__ void prep_weights(const float* __restrict__ wt) {
    int idx = blockIdx.x * 256 + threadIdx.x;
    if (idx >= 36 * 2048) return;
    int slab   = idx >> 11;
    int within = idx & 2047;
    int vi   = within & 3;           // a-reg index a0..a3
    int lane = (within >> 2) & 31;
    int kk   = (within >> 7) & 1;
    int mt   = (within >> 8) & 1;
    int mgrp = (within >> 9) & 3;
    int cg = slab / 9, rs = slab % 9;
    int k  = mgrp * 32 + mt * 16 + (lane >> 2) + (vi & 1) * 8;
    int c0 = cg * 32 + kk * 16 + (lane & 3) * 2 + (vi >> 1) * 8;
    float v0 = wt[(size_t)k * 1152 + (size_t)c0 * 9 + rs];
    float v1 = wt[(size_t)k * 1152 + (size_t)(c0 + 1) * 9 + rs];
    u32 p;
    asm("cvt.rn.f16x2.f32 %0, %1, %2;" : "=r"(p) : "f"(v1), "f"(v0));
    g_Wh[idx] = p;
}

__global__ __launch_bounds__(256, 3)
void conv_mma(const float* __restrict__ in,
              const float* __restrict__ bias,
              float* __restrict__ out)
{
    extern __shared__ u32 sm[];
    u32 sbase;
    asm("{ .reg .u64 t; cvta.to.shared.u64 t, %1; cvt.u32.u64 %0, t; }"
        : "=r"(sbase) : "l"(sm));

    const int tid = threadIdx.x;
    const int wid = tid >> 5, lid = tid & 31;
    const int lq = lid & 3, g = lid >> 2;
    const int mgrp = wid & 3;             // warp m group (32 k each)
    const int wn = wid >> 2;              // warp output row (0/1)

    const int img = blockIdx.x / 28;
    const int h0  = (blockIdx.x % 28) * 2;
    const float* in_n = in + (size_t)img * 401408;

    float acc[2][7][4];
    #pragma unroll
    for (int mt = 0; mt < 2; mt++)
        #pragma unroll
        for (int nt = 0; nt < 7; nt++)
            #pragma unroll
            for (int q = 0; q < 4; q++) acc[mt][nt][q] = 0.f;

    // ---- X loader: LDG fp32 -> cvt.rn.f16x2 -> STS (once per element) ----
    auto loadX = [&](int cg, int xb) {
        #pragma unroll 1
        for (int idx = tid; idx < 3712; idx += 256) {
            int wl  = idx % 58;
            int t   = idx / 58;
            int row = t & 3;
            int hi  = (t >> 2) & 1;
            int lq_ = (t >> 3) & 3;
            int kk_ = t >> 5;
            int hin = h0 - 1 + row;
            int win = wl - 1;
            int c0  = cg * 32 + kk_ * 16 + lq_ * 2 + hi * 8;
            float v0 = 0.f, v1 = 0.f;
            if (((unsigned)hin < 56u) & ((unsigned)win < 56u)) {
                const float* p = in_n + (size_t)c0 * 3136 + hin * 56 + win;
                v0 = __ldg(p);
                v1 = __ldg(p + 3136);
            }
            u32 pk;
            asm("cvt.rn.f16x2.f32 %0, %1, %2;" : "=r"(pk) : "f"(v1), "f"(v0));
            sm[XB(xb) + ((kk_ * 4 + lq_) * 4 + row) * 122 + wl * 2 + hi] = pk;
        }
    };

    // ---- async W loader: linear 8KB slab copy into ring slot ----
    auto prefW = [&](int s, int slot) {
        const u32* src = g_Wh + (size_t)s * 2048;
        const u32 dstb = sbase + WB(slot) * 4;
        #pragma unroll
        for (int j = 0; j < 2; j++) {
            int chunk = tid + j * 256;             // 0..511, 16B each
            asm volatile("cp.async.ca.shared.global [%0], [%1], 16;"
                         :: "r"(dstb + chunk * 16), "l"(src + chunk * 4)
                         : "memory");
        }
        asm volatile("cp.async.commit_group;" ::: "memory");
    };

    // ---- prologue ----
    loadX(0, 0);
    prefW(0, 0);
    prefW(1, 1);

    #pragma unroll 1
    for (int s = 0; s < 36; s++) {
        if (s < 35) asm volatile("cp.async.wait_group 1;" ::: "memory");
        else        asm volatile("cp.async.wait_group 0;" ::: "memory");
        __syncthreads();   // W(s) + current X visible; prior consumers done

        if (s + 2 < 36) prefW(s + 2, (s + 2) % 3);
        if (s % 9 == 5 && s / 9 + 1 < 4) loadX(s / 9 + 1, (s / 9 + 1) & 1);

        const int rs = s % 9;
        const u32* Wb = sm + WB(s % 3) + mgrp * 512 + lid * 4;
        const u32* Bb = sm + XB((s / 9) & 1) + lq * 488
                        + (wn + rs / 3) * 122 + (g + rs % 3) * 2;

        #pragma unroll
        for (int kk = 0; kk < 2; kk++) {
            u32 b[7][2];
            #pragma unroll
            for (int nt = 0; nt < 7; nt++) {
                uint2 v = *reinterpret_cast<const uint2*>(
                              Bb + kk * 1952 + nt * 16);
                b[nt][0] = v.x;
                b[nt][1] = v.y;
            }
            #pragma unroll
            for (int mt = 0; mt < 2; mt++) {
                // A frag loaded here (not hoisted) to keep liveness low
                uint4 av = *reinterpret_cast<const uint4*>(
                               Wb + mt * 256 + kk * 128);
                #pragma unroll
                for (int nt = 0; nt < 7; nt++)
                    asm volatile(
                        "mma.sync.aligned.m16n8k16.row.col.f32.f16.f16.f32 "
                        "{%0,%1,%2,%3}, {%4,%5,%6,%7}, {%8,%9}, {%0,%1,%2,%3};"
                        : "+f"(acc[mt][nt][0]), "+f"(acc[mt][nt][1]),
                          "+f"(acc[mt][nt][2]), "+f"(acc[mt][nt][3])
                        : "r"(av.x), "r"(av.y), "r"(av.z), "r"(av.w),
                          "r"(b[nt][0]), "r"(b[nt][1]));
            }
        }
    }

    // ---- epilogue: direct STG.64 + bias ----
    #pragma unroll
    for (int mt = 0; mt < 2; mt++)
        #pragma unroll
        for (int h = 0; h < 2; h++) {
            const int k = mgrp * 32 + mt * 16 + h * 8 + g;
            const float bv = __ldg(&bias[k]);
            float* op = out + (size_t)img * 401408 + (size_t)k * 3136
                        + (h0 + wn) * 56 + lq * 2;
            #pragma unroll
            for (int nt = 0; nt < 7; nt++) {
                float2 v;
                v.x = acc[mt][nt][2 * h + 0] + bv;
                v.y = acc[mt][nt][2 * h + 1] + bv;
                *reinterpret_cast<float2*>(op + nt * 8) = v;
            }
        }
}

extern "C" void kernel_launch(void* const* d_in, const int* in_sizes, int n_in,
                              void* d_out, int out_size)
{
    const float* input  = (const float*)d_in[0];
    const float* weight = (const float*)d_in[1];
    const float* bias   = (const float*)d_in[2];
    float* out = (float*)d_out;

    cudaFuncSetAttribute(conv_mma, cudaFuncAttributeMaxDynamicSharedMemorySize,
                         SMEM_BYTES);
    cudaFuncSetAttribute(conv_mma,
                         cudaFuncAttributePreferredSharedMemoryCarveout, 100);

    prep_weights<<<(36 * 2048 + 255) / 256, 256>>>(weight);
    conv_mma<<<448, 256, SMEM_BYTES>>>(input, bias, out);
}

// round 14
// speedup vs baseline: 1.7217x; 1.0625x over previous
#include <cuda_runtime.h>
#include <cstdint>

// Conv2d N=16,C=128,H=W=56,K=128,3x3,pad1 as 9 shifted GEMMs using
// mma.sync.m16n8k16.f32.f16.f16.f32 (base PTX).
// CTA = 128k x 112 pos (2 rows x 56 w), 8 warps, occ 3 (85-reg cap).
// PAIRED stages: one barrier + one cp.async group (16KB, 2 W slabs,
// 4-slot ring) per TWO stages -> half the alignment events of R13.
// X double-buffered (LDG->cvt.rn.f16x2->STS), loads at pair tops.

typedef uint32_t u32;

#define X_ELEMS 3904                 // u32 half2: [kk:2][lq:4][row:4][122]
#define W_ELEMS 2048                 // u32 per slab: [mgrp:4][mt:2][kk:2][lane:32][4]
#define XB(i)   ((i) * X_ELEMS)
#define WB(i)   (2 * X_ELEMS + (i) * W_ELEMS)
#define SMEM_BYTES ((2 * X_ELEMS + 4 * W_ELEMS) * 4)   // 64000

__device__ u32 g_Wh[36 * 2048];      // fragment-ordered fp16x2 slabs

__global__ void prep_weights(const float* __restrict__ wt) {
    int idx = blockIdx.x * 256 + threadIdx.x;
    if (idx >= 36 * 2048) return;
    int slab   = idx >> 11;
    int within = idx & 2047;
    int vi   = within & 3;           // a-reg index a0..a3
    int lane = (within >> 2) & 31;
    int kk   = (within >> 7) & 1;
    int mt   = (within >> 8) & 1;
    int mgrp = (within >> 9) & 3;
    int cg = slab / 9, rs = slab % 9;
    int k  = mgrp * 32 + mt * 16 + (lane >> 2) + (vi & 1) * 8;
    int c0 = cg * 32 + kk * 16 + (lane & 3) * 2 + (vi >> 1) * 8;
    float v0 = wt[(size_t)k * 1152 + (size_t)c0 * 9 + rs];
    float v1 = wt[(size_t)k * 1152 + (size_t)(c0 + 1) * 9 + rs];
    u32 p;
    asm("cvt.rn.f16x2.f32 %0, %1, %2;" : "=r"(p) : "f"(v1), "f"(v0));
    g_Wh[idx] = p;
}

__global__ __launch_bounds__(256, 3)
void conv_mma(const float* __restrict__ in,
              const float* __restrict__ bias,
              float* __restrict__ out)
{
    extern __shared__ u32 sm[];
    u32 sbase;
    asm("{ .reg .u64 t; cvta.to.shared.u64 t, %1; cvt.u32.u64 %0, t; }"
        : "=r"(sbase) : "l"(sm));

    const int tid = threadIdx.x;
    const int wid = tid >> 5, lid = tid & 31;
    const int lq = lid & 3, g = lid >> 2;
    const int mgrp = wid & 3;             // warp m group (32 k each)
    const int wn = wid >> 2;              // warp output row (0/1)

    const int img = blockIdx.x / 28;
    const int h0  = (blockIdx.x % 28) * 2;
    const float* in_n = in + (size_t)img * 401408;

    float acc[2][7][4];
    #pragma unroll
    for (int mt = 0; mt < 2; mt++)
        #pragma unroll
        for (int nt = 0; nt < 7; nt++)
            #pragma unroll
            for (int q = 0; q < 4; q++) acc[mt][nt][q] = 0.f;

    // ---- X loader: LDG fp32 -> cvt.rn.f16x2 -> STS; &63/>>6 indexing ----
    auto loadX = [&](int cg, int xb) {
        #pragma unroll 1
        for (int idx = tid; idx < 4096; idx += 256) {
            int wl = idx & 63;
            int t  = idx >> 6;           // 0..63
            if (wl < 58) {
                int row = t & 3;
                int hi  = (t >> 2) & 1;
                int lq_ = (t >> 3) & 3;
                int kk_ = t >> 5;
                int hin = h0 - 1 + row;
                int win = wl - 1;
                int c0  = cg * 32 + kk_ * 16 + lq_ * 2 + hi * 8;
                float v0 = 0.f, v1 = 0.f;
                if (((unsigned)hin < 56u) & ((unsigned)win < 56u)) {
                    const float* p = in_n + (size_t)c0 * 3136 + hin * 56 + win;
                    v0 = __ldg(p);
                    v1 = __ldg(p + 3136);
                }
                u32 pk;
                asm("cvt.rn.f16x2.f32 %0, %1, %2;" : "=r"(pk) : "f"(v1), "f"(v0));
                sm[XB(xb) + ((kk_ * 4 + lq_) * 4 + row) * 122 + wl * 2 + hi] = pk;
            }
        }
    };

    // ---- async W loader: pair of slabs (16KB) as ONE cp.async group ----
    auto prefWpair = [&](int p) {
        #pragma unroll
        for (int j = 0; j < 2; j++) {
            int slab = 2 * p + j;
            const u32* src = g_Wh + (size_t)slab * 2048;
            const u32 dstb = sbase + WB(slab & 3) * 4;
            #pragma unroll
            for (int c = 0; c < 2; c++) {
                int chunk = tid + c * 256;         // 0..511, 16B each
                asm volatile("cp.async.ca.shared.global [%0], [%1], 16;"
                             :: "r"(dstb + chunk * 16), "l"(src + chunk * 4)
                             : "memory");
            }
        }
        asm volatile("cp.async.commit_group;" ::: "memory");
    };

    // ---- one GEMM stage ----
    auto computeStage = [&](int s) {
        const int rs = s % 9;
        const u32* Wb = sm + WB(s & 3) + mgrp * 512 + lid * 4;
        const u32* Bb = sm + XB((s / 9) & 1) + lq * 488
                        + (wn + rs / 3) * 122 + (g + rs % 3) * 2;
        #pragma unroll
        for (int kk = 0; kk < 2; kk++) {
            u32 b[7][2];
            #pragma unroll
            for (int nt = 0; nt < 7; nt++) {
                uint2 v = *reinterpret_cast<const uint2*>(
                              Bb + kk * 1952 + nt * 16);
                b[nt][0] = v.x;
                b[nt][1] = v.y;
            }
            #pragma unroll
            for (int mt = 0; mt < 2; mt++) {
                uint4 av = *reinterpret_cast<const uint4*>(
                               Wb + mt * 256 + kk * 128);
                #pragma unroll
                for (int nt = 0; nt < 7; nt++)
                    asm volatile(
                        "mma.sync.aligned.m16n8k16.row.col.f32.f16.f16.f32 "
                        "{%0,%1,%2,%3}, {%4,%5,%6,%7}, {%8,%9}, {%0,%1,%2,%3};"
                        : "+f"(acc[mt][nt][0]), "+f"(acc[mt][nt][1]),
                          "+f"(acc[mt][nt][2]), "+f"(acc[mt][nt][3])
                        : "r"(av.x), "r"(av.y), "r"(av.z), "r"(av.w),
                          "r"(b[nt][0]), "r"(b[nt][1]));
            }
        }
    };

    // ---- prologue: G0 (slabs 0,1) + X(0) ----
    prefWpair(0);
    loadX(0, 0);
    asm volatile("cp.async.wait_group 0;" ::: "memory");
    __syncthreads();

    #pragma unroll 1
    for (int p = 0; p < 18; p++) {
        if (p > 0) {
            asm volatile("cp.async.wait_group 0;" ::: "memory");
            __syncthreads();   // G_p + any fresh X visible; prior reads done
        }
        if (p + 1 < 18) prefWpair(p + 1);   // slots freed by pair p-1 reads
        if (p == 2)      loadX(1, 1);       // consumed from s=9  (pair 4)
        else if (p == 6) loadX(2, 0);       // consumed from s=18 (pair 9)
        else if (p == 10) loadX(3, 1);      // consumed from s=27 (pair 13)

        computeStage(2 * p);
        computeStage(2 * p + 1);
    }

    // ---- epilogue: direct STG.64 + bias ----
    #pragma unroll
    for (int mt = 0; mt < 2; mt++)
        #pragma unroll
        for (int h = 0; h < 2; h++) {
            const int k = mgrp * 32 + mt * 16 + h * 8 + g;
            const float bv = __ldg(&bias[k]);
            float* op = out + (size_t)img * 401408 + (size_t)k * 3136
                        + (h0 + wn) * 56 + lq * 2;
            #pragma unroll
            for (int nt = 0; nt < 7; nt++) {
                float2 v;
                v.x = acc[mt][nt][2 * h + 0] + bv;
                v.y = acc[mt][nt][2 * h + 1] + bv;
                *reinterpret_cast<float2*>(op + nt * 8) = v;
            }
        }
}

extern "C" void kernel_launch(void* const* d_in, const int* in_sizes, int n_in,
                              void* d_out, int out_size)
{
    const float* input  = (const float*)d_in[0];
    const float* weight = (const float*)d_in[1];
    const float* bias   = (const float*)d_in[2];
    float* out = (float*)d_out;

    cudaFuncSetAttribute(conv_mma, cudaFuncAttributeMaxDynamicSharedMemorySize,
                         SMEM_BYTES);
    cudaFuncSetAttribute(conv_mma,
                         cudaFuncAttributePreferredSharedMemoryCarveout, 100);

    prep_weights<<<(36 * 2048 + 255) / 256, 256>>>(weight);
    conv_mma<<<448, 256, SMEM_BYTES>>>(input, bias, out);
}